// round 3
// baseline (speedup 1.0000x reference)
#include <cuda_runtime.h>
#include <math.h>

#define NB 4
#define NT 512
#define ND 1024
#define NF 4096
#define NE 8
#define NHEAD 16
#define DH 64
#define NTOK (NB*NT)          // 2048
#define CAP 2048              // per-expert slot capacity (worst case)
#define NSLOT (NE*CAP)        // 16384

// ---- static scratch (no runtime allocation allowed) ----
__device__ float g_ln[NTOK*ND];
__device__ float g_qkv[(size_t)NTOK*3*ND];
__device__ float g_scores[(size_t)NB*NHEAD*NT*NT];
__device__ float g_ctx[(size_t)NTOK*ND];
__device__ float g_hidden[(size_t)NSLOT*NF];
__device__ int   g_slot_token[NSLOT];
__device__ float g_slot_w[NSLOT];
__device__ int   g_count[NE];

typedef unsigned long long u64t;

// ---- packed f32x2 helpers ----
__device__ __forceinline__ u64t pack2_dup(float x){
    u64t r;
    asm("mov.b64 %0, {%1, %1};" : "=l"(r) : "f"(x));
    return r;
}
__device__ __forceinline__ void fma2(u64t& acc, u64t a, u64t b){
    asm("fma.rn.f32x2 %0, %1, %2, %0;" : "+l"(acc) : "l"(a), "l"(b));
}
__device__ __forceinline__ float2 unpack2(u64t v){
    float lo, hi;
    asm("mov.b64 {%0, %1}, %2;" : "=f"(lo), "=f"(hi) : "l"(v));
    return make_float2(lo, hi);
}

__device__ __forceinline__ float gelu_tanh(float x){
    float x3 = x*x*x;
    return 0.5f*x*(1.0f + tanhf(0.7978845608028654f*(x + 0.044715f*x3)));
}

// 8x8 register tile micro-kernel, packed f32x2 along columns.
// acc2[i][j] holds columns (tx*8+2j, tx*8+2j+1) of row ty*8+i.
__device__ __forceinline__ void mma8x8_f32x2(
    u64t acc2[8][4], const float* __restrict__ As_row,
    const float* __restrict__ Bs_row, int ty, int tx)
{
    float ra[8];
    *(float4*)&ra[0] = *(const float4*)&As_row[ty*8];
    *(float4*)&ra[4] = *(const float4*)&As_row[ty*8+4];
    ulonglong2 b01 = *(const ulonglong2*)&Bs_row[tx*8];
    ulonglong2 b23 = *(const ulonglong2*)&Bs_row[tx*8+4];
    u64t rb[4] = {b01.x, b01.y, b23.x, b23.y};
    #pragma unroll
    for(int i=0;i<8;i++){
        u64t a2 = pack2_dup(ra[i]);
        #pragma unroll
        for(int j=0;j<4;j++) fma2(acc2[i][j], a2, rb[j]);
    }
}

// ---------------- LayerNorm ----------------
__global__ void ln_kernel(const float* __restrict__ x,
                          const float* __restrict__ w,
                          const float* __restrict__ b,
                          float* __restrict__ y)
{
    int row = blockIdx.x;
    int t = threadIdx.x;
    const float* xr = x + (size_t)row*ND;
    float v[4];
    float s = 0.f;
    #pragma unroll
    for(int i=0;i<4;i++){ v[i] = xr[t + i*256]; s += v[i]; }
    __shared__ float red[256];
    red[t] = s; __syncthreads();
    for(int o=128;o>0;o>>=1){ if(t<o) red[t]+=red[t+o]; __syncthreads(); }
    float mu = red[0]*(1.0f/ND);
    __syncthreads();
    s = 0.f;
    #pragma unroll
    for(int i=0;i<4;i++){ float d=v[i]-mu; s += d*d; }
    red[t] = s; __syncthreads();
    for(int o=128;o>0;o>>=1){ if(t<o) red[t]+=red[t+o]; __syncthreads(); }
    float rstd = rsqrtf(red[0]*(1.0f/ND) + 1e-5f);
    float* yr = y + (size_t)row*ND;
    #pragma unroll
    for(int i=0;i<4;i++){
        int c = t + i*256;
        yr[c] = (v[i]-mu)*rstd*w[c] + b[c];
    }
}

// ---------------- Generic 128x128x8 GEMM: C = A@B + bias (+res) ----------------
__global__ __launch_bounds__(256) void gemm128_bias(
    const float* __restrict__ A, int lda,
    const float* __restrict__ Bm, int ldb,
    const float* __restrict__ bias,
    const float* __restrict__ res,
    float* __restrict__ C, int ldc, int K)
{
    __shared__ float As[8][132];
    __shared__ float Bs[8][132];
    const int tid=threadIdx.x, tx=tid&15, ty=tid>>4;
    const int m0=blockIdx.y*128, n0=blockIdx.x*128;
    const int arow=tid>>1, akq=(tid&1)*4;
    const int brow=tid>>5, bn=(tid&31)*4;
    const float* Ap = A + (size_t)(m0+arow)*lda + akq;
    const float* Bp = Bm + (size_t)brow*ldb + n0 + bn;
    u64t acc2[8][4] = {};
    for(int k0=0;k0<K;k0+=8){
        float4 av = *(const float4*)(Ap + k0);
        float4 bv = *(const float4*)(Bp + (size_t)k0*ldb);
        As[akq+0][arow]=av.x; As[akq+1][arow]=av.y; As[akq+2][arow]=av.z; As[akq+3][arow]=av.w;
        *(float4*)&Bs[brow][bn] = bv;
        __syncthreads();
        #pragma unroll
        for(int kk=0;kk<8;kk++)
            mma8x8_f32x2(acc2, As[kk], Bs[kk], ty, tx);
        __syncthreads();
    }
    #pragma unroll
    for(int i=0;i<8;i++){
        int m=m0+ty*8+i;
        #pragma unroll
        for(int j=0;j<4;j++){
            float2 p = unpack2(acc2[i][j]);
            int n=n0+tx*8+2*j;
            float v0 = p.x + bias[n];
            float v1 = p.y + bias[n+1];
            if(res){ v0 += res[(size_t)m*ldc+n]; v1 += res[(size_t)m*ldc+n+1]; }
            C[(size_t)m*ldc+n]   = v0;
            C[(size_t)m*ldc+n+1] = v1;
        }
    }
}

// ---------------- Attention scores: per (b,h)  S = Q @ K^T / 8 ----------------
__global__ __launch_bounds__(256) void attn_scores_kernel()
{
    __shared__ float As[8][132];
    __shared__ float Bs[8][132];
    const int bh = blockIdx.z;
    const int b = bh>>4, h = bh&15;
    const float* Q  = g_qkv + (size_t)b*NT*3*ND + h*DH;
    const float* Km = g_qkv + (size_t)b*NT*3*ND + ND + h*DH;
    float* S = g_scores + (size_t)bh*NT*NT;
    const int tid=threadIdx.x, tx=tid&15, ty=tid>>4;
    const int m0=blockIdx.y*128, n0=blockIdx.x*128;
    const int arow=tid>>1, akq=(tid&1)*4;
    const int btk=tid>>1,  bdq=(tid&1)*4;
    const float* Ap = Q + (size_t)(m0+arow)*(3*ND) + akq;
    const float* Bp = Km + (size_t)(n0+btk)*(3*ND) + bdq;
    u64t acc2[8][4] = {};
    for(int k0=0;k0<DH;k0+=8){
        float4 av = *(const float4*)(Ap + k0);
        float4 bv = *(const float4*)(Bp + k0);
        As[akq+0][arow]=av.x; As[akq+1][arow]=av.y; As[akq+2][arow]=av.z; As[akq+3][arow]=av.w;
        Bs[bdq+0][btk]=bv.x;  Bs[bdq+1][btk]=bv.y;  Bs[bdq+2][btk]=bv.z;  Bs[bdq+3][btk]=bv.w;
        __syncthreads();
        #pragma unroll
        for(int kk=0;kk<8;kk++)
            mma8x8_f32x2(acc2, As[kk], Bs[kk], ty, tx);
        __syncthreads();
    }
    #pragma unroll
    for(int i=0;i<8;i++){
        int m=m0+ty*8+i;
        #pragma unroll
        for(int j=0;j<4;j++){
            float2 p = unpack2(acc2[i][j]);
            int n=n0+tx*8+2*j;
            S[(size_t)m*NT + n]   = p.x*0.125f;
            S[(size_t)m*NT + n+1] = p.y*0.125f;
        }
    }
}

// ---------------- Softmax over rows of 512 ----------------
__global__ void softmax_kernel()
{
    int wrow = blockIdx.x*8 + (threadIdx.x>>5);
    int lane = threadIdx.x & 31;
    float* r = g_scores + (size_t)wrow*NT;
    float v[16];
    float mx = -1e30f;
    #pragma unroll
    for(int i=0;i<16;i++){ v[i] = r[lane + 32*i]; mx = fmaxf(mx, v[i]); }
    #pragma unroll
    for(int o=16;o>0;o>>=1) mx = fmaxf(mx, __shfl_xor_sync(0xffffffffu, mx, o));
    float s = 0.f;
    #pragma unroll
    for(int i=0;i<16;i++){ v[i] = expf(v[i]-mx); s += v[i]; }
    #pragma unroll
    for(int o=16;o>0;o>>=1) s += __shfl_xor_sync(0xffffffffu, s, o);
    float inv = 1.0f/s;
    #pragma unroll
    for(int i=0;i<16;i++) r[lane + 32*i] = v[i]*inv;
}

// ---------------- ctx: per (b,h)  C = P @ V  (M=512,N=64,K=512) ----------------
__global__ __launch_bounds__(256) void attn_ctx_kernel()
{
    __shared__ float As[16][68];
    __shared__ float Bs[16][68];
    const int bh = blockIdx.z;
    const int b = bh>>4, h = bh&15;
    const float* P = g_scores + (size_t)bh*NT*NT;
    const float* V = g_qkv + (size_t)b*NT*3*ND + 2*ND + h*DH;
    const int tid=threadIdx.x, tx=tid&15, ty=tid>>4;
    const int m0 = blockIdx.y*64;
    const int arow=tid>>2, akq=(tid&3)*4;
    const int brow=tid>>4, bn=(tid&15)*4;
    const float* Ap = P + (size_t)(m0+arow)*NT + akq;
    const float* Bp = V + (size_t)brow*(3*ND) + bn;
    u64t acc2[4][2] = {};
    for(int k0=0;k0<NT;k0+=16){
        float4 av = *(const float4*)(Ap + k0);
        float4 bv = *(const float4*)(Bp + (size_t)k0*(3*ND));
        As[akq+0][arow]=av.x; As[akq+1][arow]=av.y; As[akq+2][arow]=av.z; As[akq+3][arow]=av.w;
        *(float4*)&Bs[brow][bn] = bv;
        __syncthreads();
        #pragma unroll
        for(int kk=0;kk<16;kk++){
            float4 a = *(const float4*)&As[kk][ty*4];
            ulonglong2 bq = *(const ulonglong2*)&Bs[kk][tx*4];
            u64t rb[2] = {bq.x, bq.y};
            float ra[4] = {a.x, a.y, a.z, a.w};
            #pragma unroll
            for(int i=0;i<4;i++){
                u64t a2 = pack2_dup(ra[i]);
                fma2(acc2[i][0], a2, rb[0]);
                fma2(acc2[i][1], a2, rb[1]);
            }
        }
        __syncthreads();
    }
    #pragma unroll
    for(int i=0;i<4;i++){
        int q = m0 + ty*4 + i;
        #pragma unroll
        for(int j=0;j<2;j++){
            float2 p = unpack2(acc2[i][j]);
            g_ctx[(size_t)(b*NT+q)*ND + h*DH + tx*4+2*j]   = p.x;
            g_ctx[(size_t)(b*NT+q)*ND + h*DH + tx*4+2*j+1] = p.y;
        }
    }
}

// ---------------- MoE reset ----------------
__global__ void moe_reset_kernel()
{
    int i = blockIdx.x*256 + threadIdx.x;
    if(i < NSLOT) g_slot_token[i] = -1;
    if(i < NE) g_count[i] = 0;
}

// ---------------- Gate: softmax + top2 + scatter into expert buckets ----------------
__global__ void gate_kernel(const float* __restrict__ wg)
{
    int token = blockIdx.x*8 + (threadIdx.x>>5);
    int lane = threadIdx.x & 31;
    const float* t = g_ln + (size_t)token*ND;
    float acc[NE] = {};
    for(int d=lane; d<ND; d+=32){
        float td = t[d];
        const float* w = wg + d*NE;
        #pragma unroll
        for(int e=0;e<NE;e++) acc[e] += td*w[e];
    }
    #pragma unroll
    for(int e=0;e<NE;e++)
        #pragma unroll
        for(int o=16;o>0;o>>=1) acc[e] += __shfl_xor_sync(0xffffffffu, acc[e], o);
    if(lane==0){
        float mx = -1e30f;
        #pragma unroll
        for(int e=0;e<NE;e++) mx = fmaxf(mx, acc[e]);
        float p[NE], s=0.f;
        #pragma unroll
        for(int e=0;e<NE;e++){ p[e] = expf(acc[e]-mx); s += p[e]; }
        float inv = 1.0f/s;
        #pragma unroll
        for(int e=0;e<NE;e++) p[e] *= inv;
        int e0 = 0;
        #pragma unroll
        for(int e=1;e<NE;e++) if(p[e] > p[e0]) e0 = e;
        int e1 = (e0==0) ? 1 : 0;
        #pragma unroll
        for(int e=0;e<NE;e++) if(e!=e0 && p[e] > p[e1]) e1 = e;
        float w0 = p[e0], w1 = p[e1];
        float rn = 1.0f/(w0+w1);
        w0 *= rn; w1 *= rn;
        int p0 = atomicAdd(&g_count[e0], 1);
        g_slot_token[e0*CAP + p0] = token; g_slot_w[e0*CAP + p0] = w0;
        int p1 = atomicAdd(&g_count[e1], 1);
        g_slot_token[e1*CAP + p1] = token; g_slot_w[e1*CAP + p1] = w1;
    }
}

// ---------------- MoE GEMM1: hidden = gelu(gather(ln2) @ w1[e] + b1[e]) ----------------
__global__ __launch_bounds__(256) void moe_gemm1_kernel(
    const float* __restrict__ w1, const float* __restrict__ b1)
{
    const int e = blockIdx.y >> 4;
    const int rt = blockIdx.y & 15;
    const int cnt = g_count[e];
    if(rt*128 >= cnt) return;
    __shared__ float As[8][132];
    __shared__ float Bs[8][132];
    const int tid=threadIdx.x, tx=tid&15, ty=tid>>4;
    const int m0 = rt*128, n0 = blockIdx.x*128;
    const int arow=tid>>1, akq=(tid&1)*4;
    const int brow=tid>>5, bn=(tid&31)*4;
    const int tok = g_slot_token[e*CAP + m0 + arow];
    const bool avalid = (tok >= 0);
    const float* Ap = g_ln + (size_t)(avalid?tok:0)*ND + akq;
    const float* Bp = w1 + (size_t)e*ND*NF + (size_t)brow*NF + n0 + bn;
    u64t acc2[8][4] = {};
    for(int k0=0;k0<ND;k0+=8){
        float4 av = avalid ? *(const float4*)(Ap + k0) : make_float4(0.f,0.f,0.f,0.f);
        float4 bv = *(const float4*)(Bp + (size_t)k0*NF);
        As[akq+0][arow]=av.x; As[akq+1][arow]=av.y; As[akq+2][arow]=av.z; As[akq+3][arow]=av.w;
        *(float4*)&Bs[brow][bn] = bv;
        __syncthreads();
        #pragma unroll
        for(int kk=0;kk<8;kk++)
            mma8x8_f32x2(acc2, As[kk], Bs[kk], ty, tx);
        __syncthreads();
    }
    #pragma unroll
    for(int i=0;i<8;i++){
        int sl = m0 + ty*8 + i;
        #pragma unroll
        for(int j=0;j<4;j++){
            float2 p = unpack2(acc2[i][j]);
            int n = n0 + tx*8 + 2*j;
            g_hidden[(size_t)(e*CAP+sl)*NF + n]   = gelu_tanh(p.x + b1[e*NF + n]);
            g_hidden[(size_t)(e*CAP+sl)*NF + n+1] = gelu_tanh(p.y + b1[e*NF + n+1]);
        }
    }
}

// ---------------- MoE GEMM2: out += w_slot * (hidden @ w2[e] + b2[e]) ----------------
__global__ __launch_bounds__(256) void moe_gemm2_kernel(
    const float* __restrict__ w2, const float* __restrict__ b2,
    float* __restrict__ out)
{
    const int e = blockIdx.y >> 4;
    const int rt = blockIdx.y & 15;
    const int cnt = g_count[e];
    if(rt*128 >= cnt) return;
    __shared__ float As[8][132];
    __shared__ float Bs[8][132];
    const int tid=threadIdx.x, tx=tid&15, ty=tid>>4;
    const int m0 = rt*128, n0 = blockIdx.x*128;
    const int arow=tid>>1, akq=(tid&1)*4;
    const int brow=tid>>5, bn=(tid&31)*4;
    const float* Ap = g_hidden + (size_t)(e*CAP + m0 + arow)*NF + akq;
    const float* Bp = w2 + (size_t)e*NF*ND + (size_t)brow*ND + n0 + bn;
    u64t acc2[8][4] = {};
    for(int k0=0;k0<NF;k0+=8){
        float4 av = *(const float4*)(Ap + k0);
        float4 bv = *(const float4*)(Bp + (size_t)k0*ND);
        As[akq+0][arow]=av.x; As[akq+1][arow]=av.y; As[akq+2][arow]=av.z; As[akq+3][arow]=av.w;
        *(float4*)&Bs[brow][bn] = bv;
        __syncthreads();
        #pragma unroll
        for(int kk=0;kk<8;kk++)
            mma8x8_f32x2(acc2, As[kk], Bs[kk], ty, tx);
        __syncthreads();
    }
    #pragma unroll
    for(int i=0;i<8;i++){
        int sl = m0 + ty*8 + i;
        if(sl < cnt){
            int tok = g_slot_token[e*CAP + sl];
            float wslot = g_slot_w[e*CAP + sl];
            #pragma unroll
            for(int j=0;j<4;j++){
                float2 p = unpack2(acc2[i][j]);
                int n = n0 + tx*8 + 2*j;
                atomicAdd(&out[(size_t)tok*ND + n],   wslot*(p.x + b2[e*ND + n]));
                atomicAdd(&out[(size_t)tok*ND + n+1], wslot*(p.y + b2[e*ND + n+1]));
            }
        }
    }
}

// ---------------- launch ----------------
extern "C" void kernel_launch(void* const* d_in, const int* in_sizes, int n_in,
                              void* d_out, int out_size)
{
    const float* x    = (const float*)d_in[0];
    const float* ln1w = (const float*)d_in[1];
    const float* ln1b = (const float*)d_in[2];
    const float* ln2w = (const float*)d_in[3];
    const float* ln2b = (const float*)d_in[4];
    const float* wqkv = (const float*)d_in[5];
    const float* bqkv = (const float*)d_in[6];
    const float* wo   = (const float*)d_in[7];
    const float* bo   = (const float*)d_in[8];
    const float* wg   = (const float*)d_in[9];
    const float* w1   = (const float*)d_in[10];
    const float* b1   = (const float*)d_in[11];
    const float* w2   = (const float*)d_in[12];
    const float* b2   = (const float*)d_in[13];
    float* out = (float*)d_out;

    float *p_ln, *p_qkv, *p_ctx;
    cudaGetSymbolAddress((void**)&p_ln,  g_ln);
    cudaGetSymbolAddress((void**)&p_qkv, g_qkv);
    cudaGetSymbolAddress((void**)&p_ctx, g_ctx);

    ln_kernel<<<NTOK, 256>>>(x, ln1w, ln1b, p_ln);
    gemm128_bias<<<dim3(3*ND/128, NTOK/128), 256>>>(p_ln, ND, wqkv, 3*ND, bqkv, nullptr, p_qkv, 3*ND, ND);
    attn_scores_kernel<<<dim3(NT/128, NT/128, NB*NHEAD), 256>>>();
    softmax_kernel<<<(NB*NHEAD*NT)/8, 256>>>();
    attn_ctx_kernel<<<dim3(1, NT/64, NB*NHEAD), 256>>>();
    gemm128_bias<<<dim3(ND/128, NTOK/128), 256>>>(p_ctx, ND, wo, ND, bo, x, out, ND, ND);
    ln_kernel<<<NTOK, 256>>>(out, ln2w, ln2b, p_ln);
    moe_reset_kernel<<<NSLOT/256, 256>>>();
    gate_kernel<<<NTOK/8, 256>>>(wg);
    moe_gemm1_kernel<<<dim3(NF/128, NE*16), 256>>>(w1, b1);
    moe_gemm2_kernel<<<dim3(ND/128, NE*16), 256>>>(w2, b2, out);
}

// round 4
// speedup vs baseline: 2.0270x; 2.0270x over previous
#include <cuda_runtime.h>
#include <cuda_bf16.h>
#include <math.h>

#define NB 4
#define NT 512
#define ND 1024
#define NF 4096
#define NE 8
#define NHEAD 16
#define DH 64
#define NTOK (NB*NT)          // 2048
#define CAP 2048
#define NSLOT (NE*CAP)

// ---- static scratch ----
__device__ float g_ln[NTOK*ND];
__device__ float g_qkv[(size_t)NTOK*3*ND];
__device__ float g_scores[(size_t)NB*NHEAD*NT*NT];
__device__ float g_ctx[(size_t)NTOK*ND];
__device__ float g_hidden[(size_t)NSLOT*NF];
__device__ int   g_slot_token[NSLOT];
__device__ float g_slot_w[NSLOT];
__device__ int   g_count[NE];

__device__ __forceinline__ float gelu_tanh(float x){
    float x3 = x*x*x;
    return 0.5f*x*(1.0f + tanhf(0.7978845608028654f*(x + 0.044715f*x3)));
}

// ---- bf16 split-pack: two f32 -> packed hi-pair + lo-pair ----
__device__ __forceinline__ void split_pack(float x0, float x1, unsigned& hp, unsigned& lp){
    __nv_bfloat16 h0 = __float2bfloat16_rn(x0);
    __nv_bfloat16 h1 = __float2bfloat16_rn(x1);
    __nv_bfloat16 l0 = __float2bfloat16_rn(x0 - __bfloat162float(h0));
    __nv_bfloat16 l1 = __float2bfloat16_rn(x1 - __bfloat162float(h1));
    hp = ((unsigned)__bfloat16_as_ushort(h1)<<16) | (unsigned)__bfloat16_as_ushort(h0);
    lp = ((unsigned)__bfloat16_as_ushort(l1)<<16) | (unsigned)__bfloat16_as_ushort(l0);
}

__device__ __forceinline__ void mma_bf16(float* c, const unsigned* a, const unsigned* b){
    asm volatile("mma.sync.aligned.m16n8k16.row.col.f32.bf16.bf16.f32 "
        "{%0,%1,%2,%3}, {%4,%5,%6,%7}, {%8,%9}, {%0,%1,%2,%3};\n"
        : "+f"(c[0]),"+f"(c[1]),"+f"(c[2]),"+f"(c[3])
        : "r"(a[0]),"r"(a[1]),"r"(a[2]),"r"(a[3]), "r"(b[0]),"r"(b[1]));
}

// ================== bf16x3 GEMM core ==================
// BM=128 fixed. Block = GM*GN warps (=8 -> 256 threads).
// A: row-major [M,K], caller pre-offset to block row (or rmap gather of rows).
// B: if !BNK row-major [K,N] (caller pre-offset by n0);
//    if  BNK n-major [N,K]   (caller pre-offset by n0 rows).
template<int BN,int GM,int GN,int WM,int WN,bool BNK>
__device__ __forceinline__ void gemm_core_bf16x3(
    const float* __restrict__ A, int lda, const int* __restrict__ rmap,
    const float* __restrict__ B, int ldb, int K,
    float acc[WM][WN][4])
{
    constexpr int SA  = 24;               // A smem stride (bf16 elems)
    constexpr int SBk = BN + 8;           // B kn-layout stride
    constexpr int SBn = 24;               // B nk-layout stride
    constexpr int BSZ = BNK ? BN*SBn : 16*SBk;

    __shared__ __align__(16) __nv_bfloat16 AsH[128*SA], AsL[128*SA];
    __shared__ __align__(16) __nv_bfloat16 BsH[BSZ],    BsL[BSZ];

    const int tid  = threadIdx.x;
    const int lane = tid & 31, w = tid >> 5;
    const int wm = (w % GM)*(WM*16);
    const int wn = (w / GM)*(WN*8);
    const int g = lane>>2, q = lane&3;

    // ---- A staging coords: row = tid>>1, k-offset = (tid&1)*8 ----
    const int ar = tid>>1, ak = (tid&1)*8;
    const float* Ap = nullptr;
    if(rmap){ int tok = rmap[ar]; if(tok>=0) Ap = A + (size_t)tok*lda + ak; }
    else      Ap = A + (size_t)ar*lda + ak;
    const int aoff = ar*SA + ak;

    // ---- B staging coords ----
    const float* Bp;
    int boff;
    if(BNK){
        const int bnr = tid>>1, bk = (tid&1)*8;
        Bp = B + (size_t)bnr*ldb + bk;
        boff = bnr*SBn + bk;
    } else if(BN==128){
        const int bkr = tid>>4, bn = (tid&15)*8;
        Bp = B + (size_t)bkr*ldb + bn;
        boff = bkr*SBk + bn;
    } else { // BN==64
        const int bkr = tid>>4, bn = (tid&15)*4;
        Bp = B + (size_t)bkr*ldb + bn;
        boff = bkr*SBk + bn;
    }

    for(int k0=0;k0<K;k0+=16){
        // ---- stage A (128x16) ----
        {
            float4 v0, v1;
            if(Ap){ v0 = *(const float4*)(Ap + k0); v1 = *(const float4*)(Ap + k0 + 4); }
            else  { v0 = make_float4(0,0,0,0); v1 = v0; }
            unsigned h,l;
            split_pack(v0.x,v0.y,h,l); *(unsigned*)&AsH[aoff  ]=h; *(unsigned*)&AsL[aoff  ]=l;
            split_pack(v0.z,v0.w,h,l); *(unsigned*)&AsH[aoff+2]=h; *(unsigned*)&AsL[aoff+2]=l;
            split_pack(v1.x,v1.y,h,l); *(unsigned*)&AsH[aoff+4]=h; *(unsigned*)&AsL[aoff+4]=l;
            split_pack(v1.z,v1.w,h,l); *(unsigned*)&AsH[aoff+6]=h; *(unsigned*)&AsL[aoff+6]=l;
        }
        // ---- stage B (16xBN or BNx16) ----
        {
            unsigned h,l;
            if(BNK){
                float4 u0 = *(const float4*)(Bp + k0);
                float4 u1 = *(const float4*)(Bp + k0 + 4);
                split_pack(u0.x,u0.y,h,l); *(unsigned*)&BsH[boff  ]=h; *(unsigned*)&BsL[boff  ]=l;
                split_pack(u0.z,u0.w,h,l); *(unsigned*)&BsH[boff+2]=h; *(unsigned*)&BsL[boff+2]=l;
                split_pack(u1.x,u1.y,h,l); *(unsigned*)&BsH[boff+4]=h; *(unsigned*)&BsL[boff+4]=l;
                split_pack(u1.z,u1.w,h,l); *(unsigned*)&BsH[boff+6]=h; *(unsigned*)&BsL[boff+6]=l;
            } else if(BN==128){
                float4 u0 = *(const float4*)(Bp + (size_t)k0*ldb);
                float4 u1 = *(const float4*)(Bp + (size_t)k0*ldb + 4);
                split_pack(u0.x,u0.y,h,l); *(unsigned*)&BsH[boff  ]=h; *(unsigned*)&BsL[boff  ]=l;
                split_pack(u0.z,u0.w,h,l); *(unsigned*)&BsH[boff+2]=h; *(unsigned*)&BsL[boff+2]=l;
                split_pack(u1.x,u1.y,h,l); *(unsigned*)&BsH[boff+4]=h; *(unsigned*)&BsL[boff+4]=l;
                split_pack(u1.z,u1.w,h,l); *(unsigned*)&BsH[boff+6]=h; *(unsigned*)&BsL[boff+6]=l;
            } else {
                float4 u0 = *(const float4*)(Bp + (size_t)k0*ldb);
                split_pack(u0.x,u0.y,h,l); *(unsigned*)&BsH[boff  ]=h; *(unsigned*)&BsL[boff  ]=l;
                split_pack(u0.z,u0.w,h,l); *(unsigned*)&BsH[boff+2]=h; *(unsigned*)&BsL[boff+2]=l;
            }
        }
        __syncthreads();

        // ---- fragments ----
        unsigned aH[WM][4], aL[WM][4], bH[WN][2], bL[WN][2];
        #pragma unroll
        for(int i=0;i<WM;i++){
            int r0 = (wm + i*16 + g    )*SA + q*2;
            int r1 = (wm + i*16 + g + 8)*SA + q*2;
            aH[i][0]=*(const unsigned*)&AsH[r0];   aH[i][1]=*(const unsigned*)&AsH[r1];
            aH[i][2]=*(const unsigned*)&AsH[r0+8]; aH[i][3]=*(const unsigned*)&AsH[r1+8];
            aL[i][0]=*(const unsigned*)&AsL[r0];   aL[i][1]=*(const unsigned*)&AsL[r1];
            aL[i][2]=*(const unsigned*)&AsL[r0+8]; aL[i][3]=*(const unsigned*)&AsL[r1+8];
        }
        #pragma unroll
        for(int j=0;j<WN;j++){
            int n = wn + j*8 + g;
            if(BNK){
                int o = n*SBn + q*2;
                bH[j][0]=*(const unsigned*)&BsH[o]; bH[j][1]=*(const unsigned*)&BsH[o+8];
                bL[j][0]=*(const unsigned*)&BsL[o]; bL[j][1]=*(const unsigned*)&BsL[o+8];
            } else {
                const __nv_bfloat16* ph = &BsH[(q*2)*SBk + n];
                const __nv_bfloat16* pl = &BsL[(q*2)*SBk + n];
                bH[j][0] = (unsigned)__bfloat16_as_ushort(ph[0])      | ((unsigned)__bfloat16_as_ushort(ph[SBk])  <<16);
                bH[j][1] = (unsigned)__bfloat16_as_ushort(ph[8*SBk])  | ((unsigned)__bfloat16_as_ushort(ph[9*SBk])<<16);
                bL[j][0] = (unsigned)__bfloat16_as_ushort(pl[0])      | ((unsigned)__bfloat16_as_ushort(pl[SBk])  <<16);
                bL[j][1] = (unsigned)__bfloat16_as_ushort(pl[8*SBk])  | ((unsigned)__bfloat16_as_ushort(pl[9*SBk])<<16);
            }
        }
        #pragma unroll
        for(int i=0;i<WM;i++)
            #pragma unroll
            for(int j=0;j<WN;j++){
                mma_bf16(acc[i][j], aH[i], bH[j]);
                mma_bf16(acc[i][j], aH[i], bL[j]);
                mma_bf16(acc[i][j], aL[i], bH[j]);
            }
        __syncthreads();
    }
}

// ================== GEMM kernels ==================

// C = A@B + bias (+res)
__global__ __launch_bounds__(256) void tc_gemm_bias(
    const float* __restrict__ A, int lda,
    const float* __restrict__ B, int ldb,
    const float* __restrict__ bias,
    const float* __restrict__ res,
    float* __restrict__ C, int ldc, int K)
{
    const int m0 = blockIdx.y*128, n0 = blockIdx.x*128;
    float acc[4][4][4] = {};
    gemm_core_bf16x3<128,2,4,4,4,false>(A + (size_t)m0*lda, lda, nullptr, B + n0, ldb, K, acc);
    const int lane = threadIdx.x&31, w = threadIdx.x>>5;
    const int wm = (w&1)*64, wn = (w>>1)*32;
    const int g = lane>>2, q = lane&3;
    #pragma unroll
    for(int i=0;i<4;i++)
        #pragma unroll
        for(int j=0;j<4;j++)
            #pragma unroll
            for(int hh=0;hh<2;hh++){
                int row = m0 + wm + i*16 + g + hh*8;
                int col = n0 + wn + j*8 + q*2;
                float v0 = acc[i][j][hh*2]   + bias[col];
                float v1 = acc[i][j][hh*2+1] + bias[col+1];
                if(res){
                    float2 r = *(const float2*)&res[(size_t)row*ldc+col];
                    v0 += r.x; v1 += r.y;
                }
                float2 o; o.x=v0; o.y=v1;
                *(float2*)&C[(size_t)row*ldc+col] = o;
            }
}

// scores = Q @ K^T / 8  per (b,h)
__global__ __launch_bounds__(256) void tc_attn_scores()
{
    const int bh = blockIdx.z;
    const int b = bh>>4, h = bh&15;
    const float* Q  = g_qkv + (size_t)b*NT*3*ND + h*DH;
    const float* Kp = g_qkv + (size_t)b*NT*3*ND + ND + h*DH;
    float* S = g_scores + (size_t)bh*NT*NT;
    const int m0 = blockIdx.y*128, n0 = blockIdx.x*128;
    float acc[4][4][4] = {};
    gemm_core_bf16x3<128,2,4,4,4,true>(Q + (size_t)m0*(3*ND), 3*ND, nullptr,
                                       Kp + (size_t)n0*(3*ND), 3*ND, DH, acc);
    const int lane = threadIdx.x&31, w = threadIdx.x>>5;
    const int wm = (w&1)*64, wn = (w>>1)*32;
    const int g = lane>>2, q = lane&3;
    #pragma unroll
    for(int i=0;i<4;i++)
        #pragma unroll
        for(int j=0;j<4;j++)
            #pragma unroll
            for(int hh=0;hh<2;hh++){
                int row = m0 + wm + i*16 + g + hh*8;
                int col = n0 + wn + j*8 + q*2;
                float2 o;
                o.x = acc[i][j][hh*2]  *0.125f;
                o.y = acc[i][j][hh*2+1]*0.125f;
                *(float2*)&S[(size_t)row*NT+col] = o;
            }
}

// ctx = P @ V per (b,h): M=512, N=64, K=512
__global__ __launch_bounds__(256) void tc_attn_ctx()
{
    const int bh = blockIdx.z;
    const int b = bh>>4, h = bh&15;
    const float* P = g_scores + (size_t)bh*NT*NT;
    const float* V = g_qkv + (size_t)b*NT*3*ND + 2*ND + h*DH;
    const int m0 = blockIdx.y*128;
    float acc[2][4][4] = {};
    gemm_core_bf16x3<64,4,2,2,4,false>(P + (size_t)m0*NT, NT, nullptr, V, 3*ND, NT, acc);
    const int lane = threadIdx.x&31, w = threadIdx.x>>5;
    const int wm = (w&3)*32, wn = (w>>2)*32;
    const int g = lane>>2, q = lane&3;
    #pragma unroll
    for(int i=0;i<2;i++)
        #pragma unroll
        for(int j=0;j<4;j++)
            #pragma unroll
            for(int hh=0;hh<2;hh++){
                int row = m0 + wm + i*16 + g + hh*8;
                int col = wn + j*8 + q*2;
                float2 o;
                o.x = acc[i][j][hh*2];
                o.y = acc[i][j][hh*2+1];
                *(float2*)&g_ctx[(size_t)(b*NT+row)*ND + h*DH + col] = o;
            }
}

// MoE GEMM1: hidden = gelu(gather(ln2) @ w1[e] + b1[e])
__global__ __launch_bounds__(256) void tc_moe_gemm1(
    const float* __restrict__ w1, const float* __restrict__ b1)
{
    const int e = blockIdx.y >> 4;
    const int rt = blockIdx.y & 15;
    const int cnt = g_count[e];
    if(rt*128 >= cnt) return;
    const int m0 = rt*128, n0 = blockIdx.x*128;
    float acc[4][4][4] = {};
    gemm_core_bf16x3<128,2,4,4,4,false>(g_ln, ND, &g_slot_token[e*CAP + m0],
                                        w1 + (size_t)e*ND*NF + n0, NF, ND, acc);
    const int lane = threadIdx.x&31, w = threadIdx.x>>5;
    const int wm = (w&1)*64, wn = (w>>1)*32;
    const int g = lane>>2, q = lane&3;
    #pragma unroll
    for(int i=0;i<4;i++)
        #pragma unroll
        for(int j=0;j<4;j++)
            #pragma unroll
            for(int hh=0;hh<2;hh++){
                int sl  = m0 + wm + i*16 + g + hh*8;
                int col = n0 + wn + j*8 + q*2;
                float v0 = gelu_tanh(acc[i][j][hh*2]   + b1[e*NF + col]);
                float v1 = gelu_tanh(acc[i][j][hh*2+1] + b1[e*NF + col+1]);
                float2 o; o.x=v0; o.y=v1;
                *(float2*)&g_hidden[(size_t)(e*CAP+sl)*NF + col] = o;
            }
}

// MoE GEMM2: out += w_slot * (hidden @ w2[e] + b2[e])
__global__ __launch_bounds__(256) void tc_moe_gemm2(
    const float* __restrict__ w2, const float* __restrict__ b2,
    float* __restrict__ out)
{
    const int e = blockIdx.y >> 4;
    const int rt = blockIdx.y & 15;
    const int cnt = g_count[e];
    if(rt*128 >= cnt) return;
    const int m0 = rt*128, n0 = blockIdx.x*128;
    float acc[4][4][4] = {};
    gemm_core_bf16x3<128,2,4,4,4,false>(g_hidden + (size_t)(e*CAP + m0)*NF, NF, nullptr,
                                        w2 + (size_t)e*NF*ND + n0, ND, NF, acc);
    const int lane = threadIdx.x&31, w = threadIdx.x>>5;
    const int wm = (w&1)*64, wn = (w>>1)*32;
    const int g = lane>>2, q = lane&3;
    #pragma unroll
    for(int i=0;i<4;i++)
        #pragma unroll
        for(int j=0;j<4;j++)
            #pragma unroll
            for(int hh=0;hh<2;hh++){
                int sl  = m0 + wm + i*16 + g + hh*8;
                if(sl < cnt){
                    int tok = g_slot_token[e*CAP + sl];
                    float ws = g_slot_w[e*CAP + sl];
                    int col = n0 + wn + j*8 + q*2;
                    atomicAdd(&out[(size_t)tok*ND + col],   ws*(acc[i][j][hh*2]   + b2[e*ND + col]));
                    atomicAdd(&out[(size_t)tok*ND + col+1], ws*(acc[i][j][hh*2+1] + b2[e*ND + col+1]));
                }
            }
}

// ================== non-GEMM kernels (unchanged) ==================

__global__ void ln_kernel(const float* __restrict__ x,
                          const float* __restrict__ w,
                          const float* __restrict__ b,
                          float* __restrict__ y)
{
    int row = blockIdx.x;
    int t = threadIdx.x;
    const float* xr = x + (size_t)row*ND;
    float v[4];
    float s = 0.f;
    #pragma unroll
    for(int i=0;i<4;i++){ v[i] = xr[t + i*256]; s += v[i]; }
    __shared__ float red[256];
    red[t] = s; __syncthreads();
    for(int o=128;o>0;o>>=1){ if(t<o) red[t]+=red[t+o]; __syncthreads(); }
    float mu = red[0]*(1.0f/ND);
    __syncthreads();
    s = 0.f;
    #pragma unroll
    for(int i=0;i<4;i++){ float d=v[i]-mu; s += d*d; }
    red[t] = s; __syncthreads();
    for(int o=128;o>0;o>>=1){ if(t<o) red[t]+=red[t+o]; __syncthreads(); }
    float rstd = rsqrtf(red[0]*(1.0f/ND) + 1e-5f);
    float* yr = y + (size_t)row*ND;
    #pragma unroll
    for(int i=0;i<4;i++){
        int c = t + i*256;
        yr[c] = (v[i]-mu)*rstd*w[c] + b[c];
    }
}

__global__ void softmax_kernel()
{
    int wrow = blockIdx.x*8 + (threadIdx.x>>5);
    int lane = threadIdx.x & 31;
    float* r = g_scores + (size_t)wrow*NT;
    float v[16];
    float mx = -1e30f;
    #pragma unroll
    for(int i=0;i<16;i++){ v[i] = r[lane + 32*i]; mx = fmaxf(mx, v[i]); }
    #pragma unroll
    for(int o=16;o>0;o>>=1) mx = fmaxf(mx, __shfl_xor_sync(0xffffffffu, mx, o));
    float s = 0.f;
    #pragma unroll
    for(int i=0;i<16;i++){ v[i] = expf(v[i]-mx); s += v[i]; }
    #pragma unroll
    for(int o=16;o>0;o>>=1) s += __shfl_xor_sync(0xffffffffu, s, o);
    float inv = 1.0f/s;
    #pragma unroll
    for(int i=0;i<16;i++) r[lane + 32*i] = v[i]*inv;
}

__global__ void moe_reset_kernel()
{
    int i = blockIdx.x*256 + threadIdx.x;
    if(i < NSLOT) g_slot_token[i] = -1;
    if(i < NE) g_count[i] = 0;
}

__global__ void gate_kernel(const float* __restrict__ wg)
{
    int token = blockIdx.x*8 + (threadIdx.x>>5);
    int lane = threadIdx.x & 31;
    const float* t = g_ln + (size_t)token*ND;
    float acc[NE] = {};
    for(int d=lane; d<ND; d+=32){
        float td = t[d];
        const float* w = wg + d*NE;
        #pragma unroll
        for(int e=0;e<NE;e++) acc[e] += td*w[e];
    }
    #pragma unroll
    for(int e=0;e<NE;e++)
        #pragma unroll
        for(int o=16;o>0;o>>=1) acc[e] += __shfl_xor_sync(0xffffffffu, acc[e], o);
    if(lane==0){
        float mx = -1e30f;
        #pragma unroll
        for(int e=0;e<NE;e++) mx = fmaxf(mx, acc[e]);
        float p[NE], s=0.f;
        #pragma unroll
        for(int e=0;e<NE;e++){ p[e] = expf(acc[e]-mx); s += p[e]; }
        float inv = 1.0f/s;
        #pragma unroll
        for(int e=0;e<NE;e++) p[e] *= inv;
        int e0 = 0;
        #pragma unroll
        for(int e=1;e<NE;e++) if(p[e] > p[e0]) e0 = e;
        int e1 = (e0==0) ? 1 : 0;
        #pragma unroll
        for(int e=0;e<NE;e++) if(e!=e0 && p[e] > p[e1]) e1 = e;
        float w0 = p[e0], w1 = p[e1];
        float rn = 1.0f/(w0+w1);
        w0 *= rn; w1 *= rn;
        int p0 = atomicAdd(&g_count[e0], 1);
        g_slot_token[e0*CAP + p0] = token; g_slot_w[e0*CAP + p0] = w0;
        int p1 = atomicAdd(&g_count[e1], 1);
        g_slot_token[e1*CAP + p1] = token; g_slot_w[e1*CAP + p1] = w1;
    }
}

// ================== launch ==================
extern "C" void kernel_launch(void* const* d_in, const int* in_sizes, int n_in,
                              void* d_out, int out_size)
{
    const float* x    = (const float*)d_in[0];
    const float* ln1w = (const float*)d_in[1];
    const float* ln1b = (const float*)d_in[2];
    const float* ln2w = (const float*)d_in[3];
    const float* ln2b = (const float*)d_in[4];
    const float* wqkv = (const float*)d_in[5];
    const float* bqkv = (const float*)d_in[6];
    const float* wo   = (const float*)d_in[7];
    const float* bo   = (const float*)d_in[8];
    const float* wg   = (const float*)d_in[9];
    const float* w1   = (const float*)d_in[10];
    const float* b1   = (const float*)d_in[11];
    const float* w2   = (const float*)d_in[12];
    const float* b2   = (const float*)d_in[13];
    float* out = (float*)d_out;

    float *p_ln, *p_qkv, *p_ctx;
    cudaGetSymbolAddress((void**)&p_ln,  g_ln);
    cudaGetSymbolAddress((void**)&p_qkv, g_qkv);
    cudaGetSymbolAddress((void**)&p_ctx, g_ctx);

    ln_kernel<<<NTOK, 256>>>(x, ln1w, ln1b, p_ln);
    tc_gemm_bias<<<dim3(3*ND/128, NTOK/128), 256>>>(p_ln, ND, wqkv, 3*ND, bqkv, nullptr, p_qkv, 3*ND, ND);
    tc_attn_scores<<<dim3(NT/128, NT/128, NB*NHEAD), 256>>>();
    softmax_kernel<<<(NB*NHEAD*NT)/8, 256>>>();
    tc_attn_ctx<<<dim3(1, NT/128, NB*NHEAD), 256>>>();
    tc_gemm_bias<<<dim3(ND/128, NTOK/128), 256>>>(p_ctx, ND, wo, ND, bo, x, out, ND, ND);
    ln_kernel<<<NTOK, 256>>>(out, ln2w, ln2b, p_ln);
    moe_reset_kernel<<<NSLOT/256, 256>>>();
    gate_kernel<<<NTOK/8, 256>>>(wg);
    tc_moe_gemm1<<<dim3(NF/128, NE*16), 256>>>(w1, b1);
    tc_moe_gemm2<<<dim3(ND/128, NE*16), 256>>>(w2, b2, out);
}